// round 14
// baseline (speedup 1.0000x reference)
#include <cuda_runtime.h>
#include <cuda_bf16.h>
#include <math.h>

#define D_   1024
#define U_   2048
#define R_   256
#define L_   1024
#define M_   512
#define QL   2304   // U + R
#define KVL  3840   // M + R + L + U
#define NH   16
#define HD   64

// Scratch
__device__ float g_query[(size_t)QL * D_];
__device__ float g_attn[(size_t)QL * D_];

// Round-to-nearest tf32 in the integer domain: add half-ULP of bit 13.
__device__ __forceinline__ unsigned rnb(float f) {
    return __float_as_uint(f) + 0x1000u;
}
__device__ __forceinline__ uint4 rnb4(float4 v) {
    return make_uint4(rnb(v.x), rnb(v.y), rnb(v.z), rnb(v.w));
}

// ===========================================================================
// tf32 tensor-core GEMM: C(128x64) = A @ B^T (+bias), both row-major K-contig
// 256 threads = 8 warps (4m x 2n), warp tile 32x32, mma.m16n8k8.tf32.
// Software-pipelined: next k-tile's LDG issued before compute (latency hidden).
// ===========================================================================
#define BM 128
#define BN 64
#define BK 32
#define KSTR 36   // smem stride words -> fragment LDS conflict-free

__device__ __forceinline__ void mma_tf32(float c[4], unsigned a0, unsigned a1,
                                         unsigned a2, unsigned a3,
                                         unsigned b0, unsigned b1) {
    asm("mma.sync.aligned.m16n8k8.row.col.f32.tf32.tf32.f32 "
        "{%0,%1,%2,%3}, {%4,%5,%6,%7}, {%8,%9}, {%0,%1,%2,%3};"
        : "+f"(c[0]), "+f"(c[1]), "+f"(c[2]), "+f"(c[3])
        : "r"(a0), "r"(a1), "r"(a2), "r"(a3), "r"(b0), "r"(b1));
}

// arow: A row (bm + tid>>1), brow: B row (bn + tid>>2); both K-contiguous.
__device__ __forceinline__ void mma_gemm_loop(const float* __restrict__ arow,
                                              const float* __restrict__ brow,
                                              unsigned* As, unsigned* Bs, int tid,
                                              float c[2][4][4]) {
    const int lsegA = (tid & 1) * 16;   // 2 threads per A row, 16 cols each
    const int lsegB = (tid & 3) * 8;    // 4 threads per B row, 8 cols each
    const int arw = tid >> 1;
    const int brw = tid >> 2;
    const int lane = tid & 31;
    const int wid = tid >> 5;
    const int wm = (wid >> 1) * 32;
    const int wn = (wid & 1) * 32;
    const int gr = lane >> 2, tg = lane & 3;

    float4 a[4], b[2];
    // preload k-tile 0
#pragma unroll
    for (int j = 0; j < 4; j++)
        a[j] = *(const float4*)(arow + lsegA + 4 * j);
#pragma unroll
    for (int j = 0; j < 2; j++)
        b[j] = *(const float4*)(brow + lsegB + 4 * j);

    for (int kt = 0; kt < D_; kt += BK) {
        __syncthreads();
#pragma unroll
        for (int j = 0; j < 4; j++)
            *(uint4*)(As + arw * KSTR + lsegA + 4 * j) = rnb4(a[j]);
#pragma unroll
        for (int j = 0; j < 2; j++)
            *(uint4*)(Bs + brw * KSTR + lsegB + 4 * j) = rnb4(b[j]);
        // prefetch next k-tile (latency overlaps compute below)
        if (kt + BK < D_) {
#pragma unroll
            for (int j = 0; j < 4; j++)
                a[j] = *(const float4*)(arow + kt + BK + lsegA + 4 * j);
#pragma unroll
            for (int j = 0; j < 2; j++)
                b[j] = *(const float4*)(brow + kt + BK + lsegB + 4 * j);
        }
        __syncthreads();
#pragma unroll
        for (int ks = 0; ks < 4; ks++) {
            unsigned af[2][4], bf[4][2];
#pragma unroll
            for (int mi = 0; mi < 2; mi++) {
                const unsigned* ab = As + (wm + mi * 16 + gr) * KSTR + ks * 8 + tg;
                af[mi][0] = ab[0];
                af[mi][1] = ab[8 * KSTR];
                af[mi][2] = ab[4];
                af[mi][3] = ab[8 * KSTR + 4];
            }
#pragma unroll
            for (int ni = 0; ni < 4; ni++) {
                const unsigned* bb = Bs + (wn + ni * 8 + gr) * KSTR + ks * 8 + tg;
                bf[ni][0] = bb[0];
                bf[ni][1] = bb[4];
            }
#pragma unroll
            for (int mi = 0; mi < 2; mi++)
#pragma unroll
                for (int ni = 0; ni < 4; ni++)
                    mma_tf32(c[mi][ni], af[mi][0], af[mi][1], af[mi][2], af[mi][3],
                             bf[ni][0], bf[ni][1]);
        }
    }
}

// query = concat(rc, utt) @ Wq^T + bq -> g_query
__global__ __launch_bounds__(256) void gemm_q_kernel(const float* __restrict__ rc,
                                                     const float* __restrict__ utt,
                                                     const float* __restrict__ W,
                                                     const float* __restrict__ bias) {
    __shared__ __align__(16) unsigned As[BM * KSTR];
    __shared__ __align__(16) unsigned Bs[BN * KSTR];
    const int tid = threadIdx.x;
    const int bm = blockIdx.x * BM, bn = blockIdx.y * BN;
    const int arowi = bm + (tid >> 1);
    const float* arow = (arowi < R_) ? rc + (size_t)arowi * D_
                                     : utt + (size_t)(arowi - R_) * D_;
    const float* brow = W + (size_t)(bn + (tid >> 2)) * D_;
    float c[2][4][4];
#pragma unroll
    for (int a = 0; a < 2; a++)
#pragma unroll
        for (int b = 0; b < 4; b++)
#pragma unroll
            for (int d = 0; d < 4; d++) c[a][b][d] = 0.f;
    mma_gemm_loop(arow, brow, As, Bs, tid, c);
    const int lane = tid & 31;
    const int wid = tid >> 5;
    const int wm = (wid >> 1) * 32, wn = (wid & 1) * 32;
    const int gr = lane >> 2, tg = lane & 3;
#pragma unroll
    for (int ni = 0; ni < 4; ni++) {
        int col = bn + wn + ni * 8 + tg * 2;
        float2 bb = *(const float2*)(bias + col);
#pragma unroll
        for (int mi = 0; mi < 2; mi++) {
            int row = bm + wm + mi * 16 + gr;
            *(float2*)(g_query + (size_t)row * D_ + col) =
                make_float2(c[mi][ni][0] + bb.x, c[mi][ni][1] + bb.y);
            *(float2*)(g_query + (size_t)(row + 8) * D_ + col) =
                make_float2(c[mi][ni][2] + bb.x, c[mi][ni][3] + bb.y);
        }
    }
}

// kv = concat(mem, rc, utt) @ Wkv^T + bkv -> scattered into key/value buffers
__global__ __launch_bounds__(256) void gemm_kv_kernel(const float* __restrict__ mem,
                                                      const float* __restrict__ rc,
                                                      const float* __restrict__ utt,
                                                      const float* __restrict__ W,
                                                      const float* __restrict__ bias,
                                                      float* __restrict__ keyBuf,
                                                      float* __restrict__ valBuf) {
    __shared__ __align__(16) unsigned As[BM * KSTR];
    __shared__ __align__(16) unsigned Bs[BN * KSTR];
    const int tid = threadIdx.x;
    const int bm = blockIdx.x * BM, bn = blockIdx.y * BN;
    const int arowi = bm + (tid >> 1);
    const float* arow = (arowi < M_)      ? mem + (size_t)arowi * D_
                      : (arowi < M_ + R_) ? rc + (size_t)(arowi - M_) * D_
                                          : utt + (size_t)(arowi - M_ - R_) * D_;
    const float* brow = W + (size_t)(bn + (tid >> 2)) * D_;
    float c[2][4][4];
#pragma unroll
    for (int a = 0; a < 2; a++)
#pragma unroll
        for (int b = 0; b < 4; b++)
#pragma unroll
            for (int d = 0; d < 4; d++) c[a][b][d] = 0.f;
    mma_gemm_loop(arow, brow, As, Bs, tid, c);
    const int lane = tid & 31;
    const int wid = tid >> 5;
    const int wm = (wid >> 1) * 32, wn = (wid & 1) * 32;
    const int gr = lane >> 2, tg = lane & 3;
    float* obase = (bn < D_) ? keyBuf : valBuf;
    const int cb = (bn < D_) ? bn : bn - D_;
#pragma unroll
    for (int ni = 0; ni < 4; ni++) {
        int col = cb + wn + ni * 8 + tg * 2;
        float2 bb = *(const float2*)(bias + bn + wn + ni * 8 + tg * 2);
#pragma unroll
        for (int mi = 0; mi < 2; mi++) {
            int row0 = bm + wm + mi * 16 + gr;
            int ro0 = (row0 < M_ + R_) ? row0 : row0 + L_;
            int row1 = row0 + 8;
            int ro1 = (row1 < M_ + R_) ? row1 : row1 + L_;
            *(float2*)(obase + (size_t)ro0 * D_ + col) =
                make_float2(c[mi][ni][0] + bb.x, c[mi][ni][1] + bb.y);
            *(float2*)(obase + (size_t)ro1 * D_ + col) =
                make_float2(c[mi][ni][2] + bb.x, c[mi][ni][3] + bb.y);
        }
    }
}

// out = g_attn @ Wo^T + bo
__global__ __launch_bounds__(256) void gemm_o_kernel(const float* __restrict__ W,
                                                     const float* __restrict__ bias,
                                                     float* __restrict__ outBuf) {
    __shared__ __align__(16) unsigned As[BM * KSTR];
    __shared__ __align__(16) unsigned Bs[BN * KSTR];
    const int tid = threadIdx.x;
    const int bm = blockIdx.x * BM, bn = blockIdx.y * BN;
    const float* arow = g_attn + (size_t)(bm + (tid >> 1)) * D_;
    const float* brow = W + (size_t)(bn + (tid >> 2)) * D_;
    float c[2][4][4];
#pragma unroll
    for (int a = 0; a < 2; a++)
#pragma unroll
        for (int b = 0; b < 4; b++)
#pragma unroll
            for (int d = 0; d < 4; d++) c[a][b][d] = 0.f;
    mma_gemm_loop(arow, brow, As, Bs, tid, c);
    const int lane = tid & 31;
    const int wid = tid >> 5;
    const int wm = (wid >> 1) * 32, wn = (wid & 1) * 32;
    const int gr = lane >> 2, tg = lane & 3;
#pragma unroll
    for (int ni = 0; ni < 4; ni++) {
        int col = bn + wn + ni * 8 + tg * 2;
        float2 bb = *(const float2*)(bias + col);
#pragma unroll
        for (int mi = 0; mi < 2; mi++) {
            int row = bm + wm + mi * 16 + gr;
            *(float2*)(outBuf + (size_t)row * D_ + col) =
                make_float2(c[mi][ni][0] + bb.x, c[mi][ni][1] + bb.y);
            *(float2*)(outBuf + (size_t)(row + 8) * D_ + col) =
                make_float2(c[mi][ni][2] + bb.x, c[mi][ni][3] + bb.y);
        }
    }
}

// ===========================================================================
// Flash attention v9: tf32 tensor-core S and P@V, TQ=256, tf32-RN via integer
// add, software-pipelined K/V tile loads. 512 threads = 16 warps; warp w owns
// q-rows [w*16, w*16+16). kv tile 64.
// Smem: Ks[64][68], Vs[64][72], Ps[256][68] = 103 KB -> 1 CTA/SM (16 warps).
// ===========================================================================
#define AT_TQ 256
#define AT_TK 64
#define KS_STR 68   // [n][k] access: bank = 4*gr+tg -> 32 distinct
#define VS_STR 72   // [k][n] access: bank = 8*tg+gr -> 32 distinct

__global__ __launch_bounds__(512, 1) void attn_kernel(const float* __restrict__ Kg,
                                                      const float* __restrict__ Vg) {
    extern __shared__ __align__(16) unsigned smu[];
    unsigned* Ks = smu;                    // [64][KS_STR]
    unsigned* Vs = Ks + AT_TK * KS_STR;    // [64][VS_STR]
    unsigned* Ps = Vs + AT_TK * VS_STR;    // [256][KS_STR]

    const int tid = threadIdx.x;
    const int lane = tid & 31, wid = tid >> 5;
    const int gr = lane >> 2, tg = lane & 3;
    const int wm = wid * 16;               // warp's q-row strip within block
    const int qbase = blockIdx.x * AT_TQ;
    const int hoff = blockIdx.y * HD;
    const int row_lo = qbase + wm + gr;
    const int row_hi = row_lo + 8;

    // Q fragments for the whole kernel (pre-scaled by 1/sqrt(64); tf32-RN bits)
    unsigned qf[8][4];
#pragma unroll
    for (int ks = 0; ks < 8; ks++) {
        int c = hoff + ks * 8 + tg;
        qf[ks][0] = rnb(g_query[(size_t)row_lo * D_ + c] * 0.125f);
        qf[ks][1] = rnb(g_query[(size_t)row_hi * D_ + c] * 0.125f);
        qf[ks][2] = rnb(g_query[(size_t)row_lo * D_ + c + 4] * 0.125f);
        qf[ks][3] = rnb(g_query[(size_t)row_hi * D_ + c + 4] * 0.125f);
    }

    float o[8][4];
#pragma unroll
    for (int i = 0; i < 8; i++)
#pragma unroll
        for (int j = 0; j < 4; j++) o[i][j] = 0.f;
    float m_lo = -INFINITY, m_hi = -INFINITY, l_lo = 0.f, l_hi = 0.f;

    // tile-load helper indices: 2 (row, dseg) pairs per thread
    const int tr0 = tid >> 4,           tds0 = (tid & 15) * 4;
    const int tr1 = (512 + tid) >> 4,   tds1 = (tid & 15) * 4;

    // preload tile 0
    float4 kp[2], vp[2];
    kp[0] = *(const float4*)(Kg + (size_t)tr0 * D_ + hoff + tds0);
    vp[0] = *(const float4*)(Vg + (size_t)tr0 * D_ + hoff + tds0);
    kp[1] = *(const float4*)(Kg + (size_t)tr1 * D_ + hoff + tds1);
    vp[1] = *(const float4*)(Vg + (size_t)tr1 * D_ + hoff + tds1);

    for (int kt = 0; kt < KVL; kt += AT_TK) {
        __syncthreads();  // all warps done with prev Ks/Vs/Ps
        *(uint4*)(Ks + tr0 * KS_STR + tds0) = rnb4(kp[0]);
        *(uint4*)(Vs + tr0 * VS_STR + tds0) = rnb4(vp[0]);
        *(uint4*)(Ks + tr1 * KS_STR + tds1) = rnb4(kp[1]);
        *(uint4*)(Vs + tr1 * VS_STR + tds1) = rnb4(vp[1]);
        // prefetch next tile (latency overlaps compute below)
        if (kt + AT_TK < KVL) {
            const float* kb = Kg + (size_t)(kt + AT_TK) * D_ + hoff;
            const float* vb2 = Vg + (size_t)(kt + AT_TK) * D_ + hoff;
            kp[0] = *(const float4*)(kb + (size_t)tr0 * D_ + tds0);
            vp[0] = *(const float4*)(vb2 + (size_t)tr0 * D_ + tds0);
            kp[1] = *(const float4*)(kb + (size_t)tr1 * D_ + tds1);
            vp[1] = *(const float4*)(vb2 + (size_t)tr1 * D_ + tds1);
        }
        __syncthreads();

        // ---- S = Q @ K^T : warp computes 16 rows x 64 kv cols ----
        float s[8][4];
#pragma unroll
        for (int i = 0; i < 8; i++)
#pragma unroll
            for (int j = 0; j < 4; j++) s[i][j] = 0.f;
#pragma unroll
        for (int ni = 0; ni < 8; ni++) {
            const unsigned* bb = Ks + (ni * 8 + gr) * KS_STR + tg;
#pragma unroll
            for (int ks = 0; ks < 8; ks++) {
                unsigned b0 = bb[ks * 8];
                unsigned b1 = bb[ks * 8 + 4];
                mma_tf32(s[ni], qf[ks][0], qf[ks][1], qf[ks][2], qf[ks][3], b0, b1);
            }
        }

        // ---- online softmax (rows gr and gr+8; stats within quad) ----
        float mt_lo = -INFINITY, mt_hi = -INFINITY;
#pragma unroll
        for (int ni = 0; ni < 8; ni++) {
            mt_lo = fmaxf(mt_lo, fmaxf(s[ni][0], s[ni][1]));
            mt_hi = fmaxf(mt_hi, fmaxf(s[ni][2], s[ni][3]));
        }
        mt_lo = fmaxf(mt_lo, __shfl_xor_sync(0xffffffffu, mt_lo, 1));
        mt_lo = fmaxf(mt_lo, __shfl_xor_sync(0xffffffffu, mt_lo, 2));
        mt_hi = fmaxf(mt_hi, __shfl_xor_sync(0xffffffffu, mt_hi, 1));
        mt_hi = fmaxf(mt_hi, __shfl_xor_sync(0xffffffffu, mt_hi, 2));
        float mnew_lo = fmaxf(m_lo, mt_lo);
        float mnew_hi = fmaxf(m_hi, mt_hi);
        float alpha_lo = __expf(m_lo - mnew_lo);
        float alpha_hi = __expf(m_hi - mnew_hi);
        float sum_lo = 0.f, sum_hi = 0.f;
#pragma unroll
        for (int ni = 0; ni < 8; ni++) {
            s[ni][0] = __expf(s[ni][0] - mnew_lo);
            s[ni][1] = __expf(s[ni][1] - mnew_lo);
            s[ni][2] = __expf(s[ni][2] - mnew_hi);
            s[ni][3] = __expf(s[ni][3] - mnew_hi);
            sum_lo += s[ni][0] + s[ni][1];
            sum_hi += s[ni][2] + s[ni][3];
        }
        sum_lo += __shfl_xor_sync(0xffffffffu, sum_lo, 1);
        sum_lo += __shfl_xor_sync(0xffffffffu, sum_lo, 2);
        sum_hi += __shfl_xor_sync(0xffffffffu, sum_hi, 1);
        sum_hi += __shfl_xor_sync(0xffffffffu, sum_hi, 2);
        l_lo = l_lo * alpha_lo + sum_lo;
        l_hi = l_hi * alpha_hi + sum_hi;
        m_lo = mnew_lo;
        m_hi = mnew_hi;
#pragma unroll
        for (int ni = 0; ni < 8; ni++) {
            o[ni][0] *= alpha_lo; o[ni][1] *= alpha_lo;
            o[ni][2] *= alpha_hi; o[ni][3] *= alpha_hi;
        }

        // ---- write P (warp-local rows), tf32-RN bits ----
#pragma unroll
        for (int ni = 0; ni < 8; ni++) {
            int cc = ni * 8 + 2 * tg;
            *(uint2*)(Ps + (wm + gr) * KS_STR + cc) =
                make_uint2(rnb(s[ni][0]), rnb(s[ni][1]));
            *(uint2*)(Ps + (wm + gr + 8) * KS_STR + cc) =
                make_uint2(rnb(s[ni][2]), rnb(s[ni][3]));
        }
        __syncwarp();

        // ---- O += P @ V : warp computes 16 rows x 64 dims ----
#pragma unroll
        for (int ks = 0; ks < 8; ks++) {
            const unsigned* pa = Ps + (wm + gr) * KS_STR + ks * 8 + tg;
            unsigned a0 = pa[0];
            unsigned a1 = pa[8 * KS_STR];
            unsigned a2 = pa[4];
            unsigned a3 = pa[8 * KS_STR + 4];
            const unsigned* vb = Vs + (ks * 8 + tg) * VS_STR + gr;
#pragma unroll
            for (int ni = 0; ni < 8; ni++) {
                unsigned b0 = vb[ni * 8];
                unsigned b1 = vb[4 * VS_STR + ni * 8];
                mma_tf32(o[ni], a0, a1, a2, a3, b0, b1);
            }
        }
    }

    // normalize and write
    float inv_lo = 1.0f / l_lo;
    float inv_hi = 1.0f / l_hi;
#pragma unroll
    for (int ni = 0; ni < 8; ni++) {
        int col = hoff + ni * 8 + 2 * tg;
        *(float2*)(g_attn + (size_t)row_lo * D_ + col) =
            make_float2(o[ni][0] * inv_lo, o[ni][1] * inv_lo);
        *(float2*)(g_attn + (size_t)row_hi * D_ + col) =
            make_float2(o[ni][2] * inv_hi, o[ni][3] * inv_hi);
    }
}

#define ATTN_SMEM ((AT_TK * KS_STR + AT_TK * VS_STR + AT_TQ * KS_STR) * (int)sizeof(unsigned))

// ---------------------------------------------------------------------------
extern "C" void kernel_launch(void* const* d_in, const int* in_sizes, int n_in,
                              void* d_out, int out_size) {
    const float* utt = (const float*)d_in[0];
    const float* rc  = (const float*)d_in[1];
    const float* mem = (const float*)d_in[2];
    const float* lck = (const float*)d_in[3];
    const float* lcv = (const float*)d_in[4];
    const float* Wq  = (const float*)d_in[5];
    const float* bq  = (const float*)d_in[6];
    const float* Wkv = (const float*)d_in[7];
    const float* bkv = (const float*)d_in[8];
    const float* Wo  = (const float*)d_in[9];
    const float* bo  = (const float*)d_in[10];

    float* outBuf = (float*)d_out;                       // [2304,1024]
    float* keyBuf = outBuf + (size_t)QL * D_;            // [3840,1024]
    float* valBuf = keyBuf + (size_t)KVL * D_;           // [3840,1024]

    cudaFuncSetAttribute(attn_kernel, cudaFuncAttributeMaxDynamicSharedMemorySize,
                         ATTN_SMEM);

    gemm_q_kernel<<<dim3(QL / BM, D_ / BN), 256>>>(rc, utt, Wq, bq);
    gemm_kv_kernel<<<dim3((M_ + R_ + U_) / BM, 2 * D_ / BN), 256>>>(
        mem, rc, utt, Wkv, bkv, keyBuf, valBuf);
    cudaMemcpyAsync(keyBuf + (size_t)(M_ + R_) * D_, lck,
                    (size_t)L_ * D_ * sizeof(float), cudaMemcpyDeviceToDevice);
    cudaMemcpyAsync(valBuf + (size_t)(M_ + R_) * D_, lcv,
                    (size_t)L_ * D_ * sizeof(float), cudaMemcpyDeviceToDevice);
    attn_kernel<<<dim3(QL / AT_TQ, NH), 512, ATTN_SMEM>>>(keyBuf, valBuf);
    gemm_o_kernel<<<dim3(QL / BM, D_ / BN), 256>>>(Wo, bo, outBuf);
}

// round 15
// speedup vs baseline: 1.0579x; 1.0579x over previous
#include <cuda_runtime.h>
#include <cuda_bf16.h>
#include <math.h>

#define D_   1024
#define U_   2048
#define R_   256
#define L_   1024
#define M_   512
#define QL   2304   // U + R
#define KVL  3840   // M + R + L + U
#define NH   16
#define HD   64

// Scratch
__device__ float g_query[(size_t)QL * D_];
__device__ float g_attn[(size_t)QL * D_];

// Round-to-nearest tf32 in the integer domain: add half-ULP of bit 13.
__device__ __forceinline__ unsigned rnb(float f) {
    return __float_as_uint(f) + 0x1000u;
}
__device__ __forceinline__ uint4 rnb4(float4 v) {
    return make_uint4(rnb(v.x), rnb(v.y), rnb(v.z), rnb(v.w));
}

__device__ __forceinline__ void mma_tf32(float c[4], unsigned a0, unsigned a1,
                                         unsigned a2, unsigned a3,
                                         unsigned b0, unsigned b1) {
    asm("mma.sync.aligned.m16n8k8.row.col.f32.tf32.tf32.f32 "
        "{%0,%1,%2,%3}, {%4,%5,%6,%7}, {%8,%9}, {%0,%1,%2,%3};"
        : "+f"(c[0]), "+f"(c[1]), "+f"(c[2]), "+f"(c[3])
        : "r"(a0), "r"(a1), "r"(a2), "r"(a3), "r"(b0), "r"(b1));
}

__device__ __forceinline__ void ldsm4(unsigned& r0, unsigned& r1,
                                      unsigned& r2, unsigned& r3, unsigned addr) {
    asm volatile("ldmatrix.sync.aligned.m8n8.x4.shared.b16 {%0,%1,%2,%3}, [%4];"
                 : "=r"(r0), "=r"(r1), "=r"(r2), "=r"(r3) : "r"(addr));
}

// ===========================================================================
// tf32 tensor-core GEMM: C(128x64) = A @ B^T (+bias), both row-major K-contig
// 256 threads = 8 warps (4m x 2n), warp tile 32x32, mma.m16n8k8.tf32.
// Fragment loads via ldmatrix.x4 (4x fewer smem instructions).
// ===========================================================================
#define BM 128
#define BN 64
#define BK 32
#define KSTR 36   // stride ≡ 4 (mod 32): ldmatrix phases conflict-free

// arow: A row (bm + tid>>1), brow: B row (bn + tid>>2); both K-contiguous.
__device__ __forceinline__ void mma_gemm_loop(const float* __restrict__ arow,
                                              const float* __restrict__ brow,
                                              unsigned* As, unsigned* Bs, int tid,
                                              float c[2][4][4]) {
    const int lsegA = (tid & 1) * 16;   // 2 threads per A row, 16 cols each
    const int lsegB = (tid & 3) * 8;    // 4 threads per B row, 8 cols each
    const int arw = tid >> 1;
    const int brw = tid >> 2;
    const int lane = tid & 31;
    const int wid = tid >> 5;
    const int wm = (wid >> 1) * 32;
    const int wn = (wid & 1) * 32;

    const unsigned As_s = (unsigned)__cvta_generic_to_shared(As);
    const unsigned Bs_s = (unsigned)__cvta_generic_to_shared(Bs);
    // A x4: rows wm+(lane&15)(+16*mi), cols (lane>>4)*4 (+8*ks)
    const unsigned a_base =
        As_s + (((wm + (lane & 15)) * KSTR) + (lane >> 4) * 4) * 4u;
    // B x4 (two 8-col n-groups): rows wn+(lane&7)+((lane>>4)<<3)(+16*nip),
    // cols ((lane>>3)&1)*4 (+8*ks)
    const unsigned b_base =
        Bs_s + (((wn + (lane & 7) + ((lane >> 4) << 3)) * KSTR) +
                ((lane >> 3) & 1) * 4) * 4u;

    for (int kt = 0; kt < D_; kt += BK) {
        float4 a[4], b[2];
#pragma unroll
        for (int j = 0; j < 4; j++)
            a[j] = *(const float4*)(arow + kt + lsegA + 4 * j);
#pragma unroll
        for (int j = 0; j < 2; j++)
            b[j] = *(const float4*)(brow + kt + lsegB + 4 * j);
        __syncthreads();
#pragma unroll
        for (int j = 0; j < 4; j++)
            *(uint4*)(As + arw * KSTR + lsegA + 4 * j) = rnb4(a[j]);
#pragma unroll
        for (int j = 0; j < 2; j++)
            *(uint4*)(Bs + brw * KSTR + lsegB + 4 * j) = rnb4(b[j]);
        __syncthreads();
#pragma unroll
        for (int ks = 0; ks < 4; ks++) {
            unsigned af[2][4], bf[4][2];
            ldsm4(af[0][0], af[0][1], af[0][2], af[0][3], a_base + (ks * 8) * 4u);
            ldsm4(af[1][0], af[1][1], af[1][2], af[1][3],
                  a_base + (16 * KSTR + ks * 8) * 4u);
            ldsm4(bf[0][0], bf[0][1], bf[1][0], bf[1][1], b_base + (ks * 8) * 4u);
            ldsm4(bf[2][0], bf[2][1], bf[3][0], bf[3][1],
                  b_base + (16 * KSTR + ks * 8) * 4u);
#pragma unroll
            for (int mi = 0; mi < 2; mi++)
#pragma unroll
                for (int ni = 0; ni < 4; ni++)
                    mma_tf32(c[mi][ni], af[mi][0], af[mi][1], af[mi][2], af[mi][3],
                             bf[ni][0], bf[ni][1]);
        }
    }
}

// query = concat(rc, utt) @ Wq^T + bq -> g_query
__global__ __launch_bounds__(256) void gemm_q_kernel(const float* __restrict__ rc,
                                                     const float* __restrict__ utt,
                                                     const float* __restrict__ W,
                                                     const float* __restrict__ bias) {
    __shared__ __align__(16) unsigned As[BM * KSTR];
    __shared__ __align__(16) unsigned Bs[BN * KSTR];
    const int tid = threadIdx.x;
    const int bm = blockIdx.x * BM, bn = blockIdx.y * BN;
    const int arowi = bm + (tid >> 1);
    const float* arow = (arowi < R_) ? rc + (size_t)arowi * D_
                                     : utt + (size_t)(arowi - R_) * D_;
    const float* brow = W + (size_t)(bn + (tid >> 2)) * D_;
    float c[2][4][4];
#pragma unroll
    for (int a = 0; a < 2; a++)
#pragma unroll
        for (int b = 0; b < 4; b++)
#pragma unroll
            for (int d = 0; d < 4; d++) c[a][b][d] = 0.f;
    mma_gemm_loop(arow, brow, As, Bs, tid, c);
    const int lane = tid & 31;
    const int wid = tid >> 5;
    const int wm = (wid >> 1) * 32, wn = (wid & 1) * 32;
    const int gr = lane >> 2, tg = lane & 3;
#pragma unroll
    for (int ni = 0; ni < 4; ni++) {
        int col = bn + wn + ni * 8 + tg * 2;
        float2 bb = *(const float2*)(bias + col);
#pragma unroll
        for (int mi = 0; mi < 2; mi++) {
            int row = bm + wm + mi * 16 + gr;
            *(float2*)(g_query + (size_t)row * D_ + col) =
                make_float2(c[mi][ni][0] + bb.x, c[mi][ni][1] + bb.y);
            *(float2*)(g_query + (size_t)(row + 8) * D_ + col) =
                make_float2(c[mi][ni][2] + bb.x, c[mi][ni][3] + bb.y);
        }
    }
}

// kv = concat(mem, rc, utt) @ Wkv^T + bkv -> scattered into key/value buffers
__global__ __launch_bounds__(256) void gemm_kv_kernel(const float* __restrict__ mem,
                                                      const float* __restrict__ rc,
                                                      const float* __restrict__ utt,
                                                      const float* __restrict__ W,
                                                      const float* __restrict__ bias,
                                                      float* __restrict__ keyBuf,
                                                      float* __restrict__ valBuf) {
    __shared__ __align__(16) unsigned As[BM * KSTR];
    __shared__ __align__(16) unsigned Bs[BN * KSTR];
    const int tid = threadIdx.x;
    const int bm = blockIdx.x * BM, bn = blockIdx.y * BN;
    const int arowi = bm + (tid >> 1);
    const float* arow = (arowi < M_)      ? mem + (size_t)arowi * D_
                      : (arowi < M_ + R_) ? rc + (size_t)(arowi - M_) * D_
                                          : utt + (size_t)(arowi - M_ - R_) * D_;
    const float* brow = W + (size_t)(bn + (tid >> 2)) * D_;
    float c[2][4][4];
#pragma unroll
    for (int a = 0; a < 2; a++)
#pragma unroll
        for (int b = 0; b < 4; b++)
#pragma unroll
            for (int d = 0; d < 4; d++) c[a][b][d] = 0.f;
    mma_gemm_loop(arow, brow, As, Bs, tid, c);
    const int lane = tid & 31;
    const int wid = tid >> 5;
    const int wm = (wid >> 1) * 32, wn = (wid & 1) * 32;
    const int gr = lane >> 2, tg = lane & 3;
    float* obase = (bn < D_) ? keyBuf : valBuf;
    const int cb = (bn < D_) ? bn : bn - D_;
#pragma unroll
    for (int ni = 0; ni < 4; ni++) {
        int col = cb + wn + ni * 8 + tg * 2;
        float2 bb = *(const float2*)(bias + bn + wn + ni * 8 + tg * 2);
#pragma unroll
        for (int mi = 0; mi < 2; mi++) {
            int row0 = bm + wm + mi * 16 + gr;
            int ro0 = (row0 < M_ + R_) ? row0 : row0 + L_;
            int row1 = row0 + 8;
            int ro1 = (row1 < M_ + R_) ? row1 : row1 + L_;
            *(float2*)(obase + (size_t)ro0 * D_ + col) =
                make_float2(c[mi][ni][0] + bb.x, c[mi][ni][1] + bb.y);
            *(float2*)(obase + (size_t)ro1 * D_ + col) =
                make_float2(c[mi][ni][2] + bb.x, c[mi][ni][3] + bb.y);
        }
    }
}

// out = g_attn @ Wo^T + bo
__global__ __launch_bounds__(256) void gemm_o_kernel(const float* __restrict__ W,
                                                     const float* __restrict__ bias,
                                                     float* __restrict__ outBuf) {
    __shared__ __align__(16) unsigned As[BM * KSTR];
    __shared__ __align__(16) unsigned Bs[BN * KSTR];
    const int tid = threadIdx.x;
    const int bm = blockIdx.x * BM, bn = blockIdx.y * BN;
    const float* arow = g_attn + (size_t)(bm + (tid >> 1)) * D_;
    const float* brow = W + (size_t)(bn + (tid >> 2)) * D_;
    float c[2][4][4];
#pragma unroll
    for (int a = 0; a < 2; a++)
#pragma unroll
        for (int b = 0; b < 4; b++)
#pragma unroll
            for (int d = 0; d < 4; d++) c[a][b][d] = 0.f;
    mma_gemm_loop(arow, brow, As, Bs, tid, c);
    const int lane = tid & 31;
    const int wid = tid >> 5;
    const int wm = (wid >> 1) * 32, wn = (wid & 1) * 32;
    const int gr = lane >> 2, tg = lane & 3;
#pragma unroll
    for (int ni = 0; ni < 4; ni++) {
        int col = bn + wn + ni * 8 + tg * 2;
        float2 bb = *(const float2*)(bias + col);
#pragma unroll
        for (int mi = 0; mi < 2; mi++) {
            int row = bm + wm + mi * 16 + gr;
            *(float2*)(outBuf + (size_t)row * D_ + col) =
                make_float2(c[mi][ni][0] + bb.x, c[mi][ni][1] + bb.y);
            *(float2*)(outBuf + (size_t)(row + 8) * D_ + col) =
                make_float2(c[mi][ni][2] + bb.x, c[mi][ni][3] + bb.y);
        }
    }
}

// ===========================================================================
// Flash attention v10: tf32 mma, TQ=256, tf32-RN int rounding, prefetched
// K/V tile loads (kept: helped in round 14), ldmatrix for Ks and Ps frags.
// 512 threads = 16 warps; warp w owns q-rows [w*16, w*16+16). kv tile 64.
// Smem: Ks[64][68], Vs[64][72], Ps[256][68] = 103 KB -> 1 CTA/SM.
// ===========================================================================
#define AT_TQ 256
#define AT_TK 64
#define KS_STR 68   // ≡ 4 (mod 32): ldmatrix phases + scalar walks conflict-free
#define VS_STR 72   // [k][n] scalar access: bank = 8*tg+gr -> 32 distinct

__global__ __launch_bounds__(512, 1) void attn_kernel(const float* __restrict__ Kg,
                                                      const float* __restrict__ Vg) {
    extern __shared__ __align__(16) unsigned smu[];
    unsigned* Ks = smu;                    // [64][KS_STR]
    unsigned* Vs = Ks + AT_TK * KS_STR;    // [64][VS_STR]
    unsigned* Ps = Vs + AT_TK * VS_STR;    // [256][KS_STR]

    const int tid = threadIdx.x;
    const int lane = tid & 31, wid = tid >> 5;
    const int gr = lane >> 2, tg = lane & 3;
    const int wm = wid * 16;               // warp's q-row strip within block
    const int qbase = blockIdx.x * AT_TQ;
    const int hoff = blockIdx.y * HD;
    const int row_lo = qbase + wm + gr;
    const int row_hi = row_lo + 8;

    // ldmatrix bases
    const unsigned Ks_s = (unsigned)__cvta_generic_to_shared(Ks);
    const unsigned Ps_s = (unsigned)__cvta_generic_to_shared(Ps);
    // Ks x4 (two 8-col n-groups per call)
    const unsigned kb_base =
        Ks_s + ((((lane & 7) + ((lane >> 4) << 3)) * KS_STR) +
                ((lane >> 3) & 1) * 4) * 4u;
    // Ps x4 (A-fragment of warp's 16 q-rows)
    const unsigned p_base =
        Ps_s + (((wm + (lane & 15)) * KS_STR) + (lane >> 4) * 4) * 4u;

    // Q fragments for the whole kernel (pre-scaled by 1/sqrt(64); tf32-RN bits)
    unsigned qf[8][4];
#pragma unroll
    for (int ks = 0; ks < 8; ks++) {
        int c = hoff + ks * 8 + tg;
        qf[ks][0] = rnb(g_query[(size_t)row_lo * D_ + c] * 0.125f);
        qf[ks][1] = rnb(g_query[(size_t)row_hi * D_ + c] * 0.125f);
        qf[ks][2] = rnb(g_query[(size_t)row_lo * D_ + c + 4] * 0.125f);
        qf[ks][3] = rnb(g_query[(size_t)row_hi * D_ + c + 4] * 0.125f);
    }

    float o[8][4];
#pragma unroll
    for (int i = 0; i < 8; i++)
#pragma unroll
        for (int j = 0; j < 4; j++) o[i][j] = 0.f;
    float m_lo = -INFINITY, m_hi = -INFINITY, l_lo = 0.f, l_hi = 0.f;

    // tile-load helper indices: 2 (row, dseg) pairs per thread
    const int tr0 = tid >> 4,           tds0 = (tid & 15) * 4;
    const int tr1 = (512 + tid) >> 4,   tds1 = (tid & 15) * 4;

    // preload tile 0
    float4 kp[2], vp[2];
    kp[0] = *(const float4*)(Kg + (size_t)tr0 * D_ + hoff + tds0);
    vp[0] = *(const float4*)(Vg + (size_t)tr0 * D_ + hoff + tds0);
    kp[1] = *(const float4*)(Kg + (size_t)tr1 * D_ + hoff + tds1);
    vp[1] = *(const float4*)(Vg + (size_t)tr1 * D_ + hoff + tds1);

    for (int kt = 0; kt < KVL; kt += AT_TK) {
        __syncthreads();  // all warps done with prev Ks/Vs/Ps
        *(uint4*)(Ks + tr0 * KS_STR + tds0) = rnb4(kp[0]);
        *(uint4*)(Vs + tr0 * VS_STR + tds0) = rnb4(vp[0]);
        *(uint4*)(Ks + tr1 * KS_STR + tds1) = rnb4(kp[1]);
        *(uint4*)(Vs + tr1 * VS_STR + tds1) = rnb4(vp[1]);
        // prefetch next tile (latency overlaps compute below)
        if (kt + AT_TK < KVL) {
            const float* kb = Kg + (size_t)(kt + AT_TK) * D_ + hoff;
            const float* vb2 = Vg + (size_t)(kt + AT_TK) * D_ + hoff;
            kp[0] = *(const float4*)(kb + (size_t)tr0 * D_ + tds0);
            vp[0] = *(const float4*)(vb2 + (size_t)tr0 * D_ + tds0);
            kp[1] = *(const float4*)(kb + (size_t)tr1 * D_ + tds1);
            vp[1] = *(const float4*)(vb2 + (size_t)tr1 * D_ + tds1);
        }
        __syncthreads();

        // ---- S = Q @ K^T : warp computes 16 rows x 64 kv cols ----
        float s[8][4];
#pragma unroll
        for (int i = 0; i < 8; i++)
#pragma unroll
            for (int j = 0; j < 4; j++) s[i][j] = 0.f;
#pragma unroll
        for (int ks = 0; ks < 8; ks++) {
#pragma unroll
            for (int nip = 0; nip < 4; nip++) {
                unsigned b0, b1, b2, b3;
                ldsm4(b0, b1, b2, b3,
                      kb_base + (nip * 16 * KS_STR + ks * 8) * 4u);
                mma_tf32(s[2 * nip], qf[ks][0], qf[ks][1], qf[ks][2], qf[ks][3],
                         b0, b1);
                mma_tf32(s[2 * nip + 1], qf[ks][0], qf[ks][1], qf[ks][2], qf[ks][3],
                         b2, b3);
            }
        }

        // ---- online softmax (rows gr and gr+8; stats within quad) ----
        float mt_lo = -INFINITY, mt_hi = -INFINITY;
#pragma unroll
        for (int ni = 0; ni < 8; ni++) {
            mt_lo = fmaxf(mt_lo, fmaxf(s[ni][0], s[ni][1]));
            mt_hi = fmaxf(mt_hi, fmaxf(s[ni][2], s[ni][3]));
        }
        mt_lo = fmaxf(mt_lo, __shfl_xor_sync(0xffffffffu, mt_lo, 1));
        mt_lo = fmaxf(mt_lo, __shfl_xor_sync(0xffffffffu, mt_lo, 2));
        mt_hi = fmaxf(mt_hi, __shfl_xor_sync(0xffffffffu, mt_hi, 1));
        mt_hi = fmaxf(mt_hi, __shfl_xor_sync(0xffffffffu, mt_hi, 2));
        float mnew_lo = fmaxf(m_lo, mt_lo);
        float mnew_hi = fmaxf(m_hi, mt_hi);
        float alpha_lo = __expf(m_lo - mnew_lo);
        float alpha_hi = __expf(m_hi - mnew_hi);
        float sum_lo = 0.f, sum_hi = 0.f;
#pragma unroll
        for (int ni = 0; ni < 8; ni++) {
            s[ni][0] = __expf(s[ni][0] - mnew_lo);
            s[ni][1] = __expf(s[ni][1] - mnew_lo);
            s[ni][2] = __expf(s[ni][2] - mnew_hi);
            s[ni][3] = __expf(s[ni][3] - mnew_hi);
            sum_lo += s[ni][0] + s[ni][1];
            sum_hi += s[ni][2] + s[ni][3];
        }
        sum_lo += __shfl_xor_sync(0xffffffffu, sum_lo, 1);
        sum_lo += __shfl_xor_sync(0xffffffffu, sum_lo, 2);
        sum_hi += __shfl_xor_sync(0xffffffffu, sum_hi, 1);
        sum_hi += __shfl_xor_sync(0xffffffffu, sum_hi, 2);
        l_lo = l_lo * alpha_lo + sum_lo;
        l_hi = l_hi * alpha_hi + sum_hi;
        m_lo = mnew_lo;
        m_hi = mnew_hi;
#pragma unroll
        for (int ni = 0; ni < 8; ni++) {
            o[ni][0] *= alpha_lo; o[ni][1] *= alpha_lo;
            o[ni][2] *= alpha_hi; o[ni][3] *= alpha_hi;
        }

        // ---- write P (warp-local rows), tf32-RN bits ----
#pragma unroll
        for (int ni = 0; ni < 8; ni++) {
            int cc = ni * 8 + 2 * tg;
            *(uint2*)(Ps + (wm + gr) * KS_STR + cc) =
                make_uint2(rnb(s[ni][0]), rnb(s[ni][1]));
            *(uint2*)(Ps + (wm + gr + 8) * KS_STR + cc) =
                make_uint2(rnb(s[ni][2]), rnb(s[ni][3]));
        }
        __syncwarp();

        // ---- O += P @ V : warp computes 16 rows x 64 dims ----
#pragma unroll
        for (int ks = 0; ks < 8; ks++) {
            unsigned a0, a1, a2, a3;
            ldsm4(a0, a1, a2, a3, p_base + (ks * 8) * 4u);
            const unsigned* vb = Vs + (ks * 8 + tg) * VS_STR + gr;
#pragma unroll
            for (int ni = 0; ni < 8; ni++) {
                unsigned b0 = vb[ni * 8];
                unsigned b1 = vb[4 * VS_STR + ni * 8];
                mma_tf32(o[ni], a0, a1, a2, a3, b0, b1);
            }
        }
    }

    // normalize and write
    float inv_lo = 1.0f / l_lo;
    float inv_hi = 1.0f / l_hi;
#pragma unroll
    for (int ni = 0; ni < 8; ni++) {
        int col = hoff + ni * 8 + 2 * tg;
        *(float2*)(g_attn + (size_t)row_lo * D_ + col) =
            make_float2(o[ni][0] * inv_lo, o[ni][1] * inv_lo);
        *(float2*)(g_attn + (size_t)row_hi * D_ + col) =
            make_float2(o[ni][2] * inv_hi, o[ni][3] * inv_hi);
    }
}

#define ATTN_SMEM ((AT_TK * KS_STR + AT_TK * VS_STR + AT_TQ * KS_STR) * (int)sizeof(unsigned))

// ---------------------------------------------------------------------------
extern "C" void kernel_launch(void* const* d_in, const int* in_sizes, int n_in,
                              void* d_out, int out_size) {
    const float* utt = (const float*)d_in[0];
    const float* rc  = (const float*)d_in[1];
    const float* mem = (const float*)d_in[2];
    const float* lck = (const float*)d_in[3];
    const float* lcv = (const float*)d_in[4];
    const float* Wq  = (const float*)d_in[5];
    const float* bq  = (const float*)d_in[6];
    const float* Wkv = (const float*)d_in[7];
    const float* bkv = (const float*)d_in[8];
    const float* Wo  = (const float*)d_in[9];
    const float* bo  = (const float*)d_in[10];

    float* outBuf = (float*)d_out;                       // [2304,1024]
    float* keyBuf = outBuf + (size_t)QL * D_;            // [3840,1024]
    float* valBuf = keyBuf + (size_t)KVL * D_;           // [3840,1024]

    cudaFuncSetAttribute(attn_kernel, cudaFuncAttributeMaxDynamicSharedMemorySize,
                         ATTN_SMEM);

    gemm_q_kernel<<<dim3(QL / BM, D_ / BN), 256>>>(rc, utt, Wq, bq);
    gemm_kv_kernel<<<dim3((M_ + R_ + U_) / BM, 2 * D_ / BN), 256>>>(
        mem, rc, utt, Wkv, bkv, keyBuf, valBuf);
    cudaMemcpyAsync(keyBuf + (size_t)(M_ + R_) * D_, lck,
                    (size_t)L_ * D_ * sizeof(float), cudaMemcpyDeviceToDevice);
    cudaMemcpyAsync(valBuf + (size_t)(M_ + R_) * D_, lcv,
                    (size_t)L_ * D_ * sizeof(float), cudaMemcpyDeviceToDevice);
    attn_kernel<<<dim3(QL / AT_TQ, NH), 512, ATTN_SMEM>>>(keyBuf, valBuf);
    gemm_o_kernel<<<dim3(QL / BM, D_ / BN), 256>>>(Wo, bo, outBuf);
}

// round 16
// speedup vs baseline: 1.0717x; 1.0131x over previous
#include <cuda_runtime.h>
#include <cuda_bf16.h>
#include <math.h>

#define D_   1024
#define U_   2048
#define R_   256
#define L_   1024
#define M_   512
#define QL   2304   // U + R
#define KVL  3840   // M + R + L + U
#define NH   16
#define HD   64

// Scratch
__device__ float g_query[(size_t)QL * D_];
__device__ float g_attn[(size_t)QL * D_];

// Round-to-nearest tf32 in the integer domain: add half-ULP of bit 13.
__device__ __forceinline__ unsigned rnb(float f) {
    return __float_as_uint(f) + 0x1000u;
}
__device__ __forceinline__ uint4 rnb4(float4 v) {
    return make_uint4(rnb(v.x), rnb(v.y), rnb(v.z), rnb(v.w));
}

__device__ __forceinline__ void mma_tf32(float c[4], unsigned a0, unsigned a1,
                                         unsigned a2, unsigned a3,
                                         unsigned b0, unsigned b1) {
    asm("mma.sync.aligned.m16n8k8.row.col.f32.tf32.tf32.f32 "
        "{%0,%1,%2,%3}, {%4,%5,%6,%7}, {%8,%9}, {%0,%1,%2,%3};"
        : "+f"(c[0]), "+f"(c[1]), "+f"(c[2]), "+f"(c[3])
        : "r"(a0), "r"(a1), "r"(a2), "r"(a3), "r"(b0), "r"(b1));
}

__device__ __forceinline__ void ldsm4(unsigned& r0, unsigned& r1,
                                      unsigned& r2, unsigned& r3, unsigned addr) {
    asm volatile("ldmatrix.sync.aligned.m8n8.x4.shared.b16 {%0,%1,%2,%3}, [%4];"
                 : "=r"(r0), "=r"(r1), "=r"(r2), "=r"(r3) : "r"(addr));
}

__device__ __forceinline__ void cpasync16(unsigned dst, const void* src) {
    asm volatile("cp.async.cg.shared.global [%0], [%1], 16;"
                 :: "r"(dst), "l"(src));
}
#define CP_COMMIT() asm volatile("cp.async.commit_group;" ::: "memory")
#define CP_WAIT0()  asm volatile("cp.async.wait_group 0;" ::: "memory")

// ===========================================================================
// tf32 tensor-core GEMM: C(128x64) = A @ B^T (+bias), both row-major K-contig
// 256 threads = 8 warps (4m x 2n), warp tile 32x32, mma.m16n8k8.tf32.
// cp.async double-buffered mainloop (load latency overlaps compute; one
// barrier per k-tile). tf32-RN applied on fragment regs (+0x1000 IADD).
// ===========================================================================
#define BM 128
#define BN 64
#define BK 32
#define KSTR 36   // stride ≡ 4 (mod 32): ldmatrix phases conflict-free
#define GEMM_SMEM (2 * (BM + BN) * KSTR * (int)sizeof(unsigned))

// arow: A row (bm + tid>>1), brow: B row (bn + tid>>2); both K-contiguous.
__device__ __forceinline__ void mma_gemm_loop(const float* __restrict__ arow,
                                              const float* __restrict__ brow,
                                              unsigned* As, unsigned* Bs, int tid,
                                              float c[2][4][4]) {
    const int lsegA = (tid & 1) * 16;   // 2 threads per A row, 16 cols each
    const int lsegB = (tid & 3) * 8;    // 4 threads per B row, 8 cols each
    const int arw = tid >> 1;
    const int brw = tid >> 2;
    const int lane = tid & 31;
    const int wid = tid >> 5;
    const int wm = (wid >> 1) * 32;
    const int wn = (wid & 1) * 32;

    const unsigned As_s = (unsigned)__cvta_generic_to_shared(As);
    const unsigned Bs_s = (unsigned)__cvta_generic_to_shared(Bs);
    const unsigned ASTG = BM * KSTR * 4u;   // stage stride bytes
    const unsigned BSTG = BN * KSTR * 4u;
    const unsigned a_dst = As_s + (arw * KSTR + lsegA) * 4u;
    const unsigned b_dst = Bs_s + (brw * KSTR + lsegB) * 4u;
    const unsigned a_base =
        As_s + (((wm + (lane & 15)) * KSTR) + (lane >> 4) * 4) * 4u;
    const unsigned b_base =
        Bs_s + (((wn + (lane & 7) + ((lane >> 4) << 3)) * KSTR) +
                ((lane >> 3) & 1) * 4) * 4u;

    // prologue: tile 0 -> stage 0
#pragma unroll
    for (int j = 0; j < 4; j++)
        cpasync16(a_dst + j * 16u, arow + lsegA + 4 * j);
#pragma unroll
    for (int j = 0; j < 2; j++)
        cpasync16(b_dst + j * 16u, brow + lsegB + 4 * j);
    CP_COMMIT();

    unsigned stage = 0;
    for (int kt = 0; kt < D_; kt += BK) {
        CP_WAIT0();
        __syncthreads();   // tile kt visible to all; prev compute on other stage done
        if (kt + BK < D_) {
            unsigned ns = stage ^ 1u;
#pragma unroll
            for (int j = 0; j < 4; j++)
                cpasync16(a_dst + ns * ASTG + j * 16u, arow + kt + BK + lsegA + 4 * j);
#pragma unroll
            for (int j = 0; j < 2; j++)
                cpasync16(b_dst + ns * BSTG + j * 16u, brow + kt + BK + lsegB + 4 * j);
            CP_COMMIT();
        }
        const unsigned aoff = stage * ASTG, boff = stage * BSTG;
#pragma unroll
        for (int ks = 0; ks < 4; ks++) {
            unsigned af[2][4], bf[4][2];
            ldsm4(af[0][0], af[0][1], af[0][2], af[0][3],
                  a_base + aoff + (ks * 8) * 4u);
            ldsm4(af[1][0], af[1][1], af[1][2], af[1][3],
                  a_base + aoff + (16 * KSTR + ks * 8) * 4u);
            ldsm4(bf[0][0], bf[0][1], bf[1][0], bf[1][1],
                  b_base + boff + (ks * 8) * 4u);
            ldsm4(bf[2][0], bf[2][1], bf[3][0], bf[3][1],
                  b_base + boff + (16 * KSTR + ks * 8) * 4u);
            // tf32-RN rounding on fragment registers
#pragma unroll
            for (int mi = 0; mi < 2; mi++)
#pragma unroll
                for (int j = 0; j < 4; j++) af[mi][j] += 0x1000u;
#pragma unroll
            for (int ni = 0; ni < 4; ni++) {
                bf[ni][0] += 0x1000u;
                bf[ni][1] += 0x1000u;
            }
#pragma unroll
            for (int mi = 0; mi < 2; mi++)
#pragma unroll
                for (int ni = 0; ni < 4; ni++)
                    mma_tf32(c[mi][ni], af[mi][0], af[mi][1], af[mi][2], af[mi][3],
                             bf[ni][0], bf[ni][1]);
        }
        stage ^= 1u;
    }
}

// query = concat(rc, utt) @ Wq^T + bq -> g_query
__global__ __launch_bounds__(256) void gemm_q_kernel(const float* __restrict__ rc,
                                                     const float* __restrict__ utt,
                                                     const float* __restrict__ W,
                                                     const float* __restrict__ bias) {
    extern __shared__ __align__(16) unsigned gsm[];
    unsigned* As = gsm;
    unsigned* Bs = gsm + 2 * BM * KSTR;
    const int tid = threadIdx.x;
    const int bm = blockIdx.x * BM, bn = blockIdx.y * BN;
    const int arowi = bm + (tid >> 1);
    const float* arow = (arowi < R_) ? rc + (size_t)arowi * D_
                                     : utt + (size_t)(arowi - R_) * D_;
    const float* brow = W + (size_t)(bn + (tid >> 2)) * D_;
    float c[2][4][4];
#pragma unroll
    for (int a = 0; a < 2; a++)
#pragma unroll
        for (int b = 0; b < 4; b++)
#pragma unroll
            for (int d = 0; d < 4; d++) c[a][b][d] = 0.f;
    mma_gemm_loop(arow, brow, As, Bs, tid, c);
    const int lane = tid & 31;
    const int wid = tid >> 5;
    const int wm = (wid >> 1) * 32, wn = (wid & 1) * 32;
    const int gr = lane >> 2, tg = lane & 3;
#pragma unroll
    for (int ni = 0; ni < 4; ni++) {
        int col = bn + wn + ni * 8 + tg * 2;
        float2 bb = *(const float2*)(bias + col);
#pragma unroll
        for (int mi = 0; mi < 2; mi++) {
            int row = bm + wm + mi * 16 + gr;
            *(float2*)(g_query + (size_t)row * D_ + col) =
                make_float2(c[mi][ni][0] + bb.x, c[mi][ni][1] + bb.y);
            *(float2*)(g_query + (size_t)(row + 8) * D_ + col) =
                make_float2(c[mi][ni][2] + bb.x, c[mi][ni][3] + bb.y);
        }
    }
}

// kv = concat(mem, rc, utt) @ Wkv^T + bkv -> scattered into key/value buffers
__global__ __launch_bounds__(256) void gemm_kv_kernel(const float* __restrict__ mem,
                                                      const float* __restrict__ rc,
                                                      const float* __restrict__ utt,
                                                      const float* __restrict__ W,
                                                      const float* __restrict__ bias,
                                                      float* __restrict__ keyBuf,
                                                      float* __restrict__ valBuf) {
    extern __shared__ __align__(16) unsigned gsm[];
    unsigned* As = gsm;
    unsigned* Bs = gsm + 2 * BM * KSTR;
    const int tid = threadIdx.x;
    const int bm = blockIdx.x * BM, bn = blockIdx.y * BN;
    const int arowi = bm + (tid >> 1);
    const float* arow = (arowi < M_)      ? mem + (size_t)arowi * D_
                      : (arowi < M_ + R_) ? rc + (size_t)(arowi - M_) * D_
                                          : utt + (size_t)(arowi - M_ - R_) * D_;
    const float* brow = W + (size_t)(bn + (tid >> 2)) * D_;
    float c[2][4][4];
#pragma unroll
    for (int a = 0; a < 2; a++)
#pragma unroll
        for (int b = 0; b < 4; b++)
#pragma unroll
            for (int d = 0; d < 4; d++) c[a][b][d] = 0.f;
    mma_gemm_loop(arow, brow, As, Bs, tid, c);
    const int lane = tid & 31;
    const int wid = tid >> 5;
    const int wm = (wid >> 1) * 32, wn = (wid & 1) * 32;
    const int gr = lane >> 2, tg = lane & 3;
    float* obase = (bn < D_) ? keyBuf : valBuf;
    const int cb = (bn < D_) ? bn : bn - D_;
#pragma unroll
    for (int ni = 0; ni < 4; ni++) {
        int col = cb + wn + ni * 8 + tg * 2;
        float2 bb = *(const float2*)(bias + bn + wn + ni * 8 + tg * 2);
#pragma unroll
        for (int mi = 0; mi < 2; mi++) {
            int row0 = bm + wm + mi * 16 + gr;
            int ro0 = (row0 < M_ + R_) ? row0 : row0 + L_;
            int row1 = row0 + 8;
            int ro1 = (row1 < M_ + R_) ? row1 : row1 + L_;
            *(float2*)(obase + (size_t)ro0 * D_ + col) =
                make_float2(c[mi][ni][0] + bb.x, c[mi][ni][1] + bb.y);
            *(float2*)(obase + (size_t)ro1 * D_ + col) =
                make_float2(c[mi][ni][2] + bb.x, c[mi][ni][3] + bb.y);
        }
    }
}

// out = g_attn @ Wo^T + bo
__global__ __launch_bounds__(256) void gemm_o_kernel(const float* __restrict__ W,
                                                     const float* __restrict__ bias,
                                                     float* __restrict__ outBuf) {
    extern __shared__ __align__(16) unsigned gsm[];
    unsigned* As = gsm;
    unsigned* Bs = gsm + 2 * BM * KSTR;
    const int tid = threadIdx.x;
    const int bm = blockIdx.x * BM, bn = blockIdx.y * BN;
    const float* arow = g_attn + (size_t)(bm + (tid >> 1)) * D_;
    const float* brow = W + (size_t)(bn + (tid >> 2)) * D_;
    float c[2][4][4];
#pragma unroll
    for (int a = 0; a < 2; a++)
#pragma unroll
        for (int b = 0; b < 4; b++)
#pragma unroll
            for (int d = 0; d < 4; d++) c[a][b][d] = 0.f;
    mma_gemm_loop(arow, brow, As, Bs, tid, c);
    const int lane = tid & 31;
    const int wid = tid >> 5;
    const int wm = (wid >> 1) * 32, wn = (wid & 1) * 32;
    const int gr = lane >> 2, tg = lane & 3;
#pragma unroll
    for (int ni = 0; ni < 4; ni++) {
        int col = bn + wn + ni * 8 + tg * 2;
        float2 bb = *(const float2*)(bias + col);
#pragma unroll
        for (int mi = 0; mi < 2; mi++) {
            int row = bm + wm + mi * 16 + gr;
            *(float2*)(outBuf + (size_t)row * D_ + col) =
                make_float2(c[mi][ni][0] + bb.x, c[mi][ni][1] + bb.y);
            *(float2*)(outBuf + (size_t)(row + 8) * D_ + col) =
                make_float2(c[mi][ni][2] + bb.x, c[mi][ni][3] + bb.y);
        }
    }
}

// ===========================================================================
// Flash attention v10 (unchanged from round 15): tf32 mma, TQ=256, tf32-RN,
// register-prefetched K/V tiles, ldmatrix for Ks and Ps fragments.
// ===========================================================================
#define AT_TQ 256
#define AT_TK 64
#define KS_STR 68
#define VS_STR 72

__global__ __launch_bounds__(512, 1) void attn_kernel(const float* __restrict__ Kg,
                                                      const float* __restrict__ Vg) {
    extern __shared__ __align__(16) unsigned smu[];
    unsigned* Ks = smu;                    // [64][KS_STR]
    unsigned* Vs = Ks + AT_TK * KS_STR;    // [64][VS_STR]
    unsigned* Ps = Vs + AT_TK * VS_STR;    // [256][KS_STR]

    const int tid = threadIdx.x;
    const int lane = tid & 31, wid = tid >> 5;
    const int gr = lane >> 2, tg = lane & 3;
    const int wm = wid * 16;
    const int qbase = blockIdx.x * AT_TQ;
    const int hoff = blockIdx.y * HD;
    const int row_lo = qbase + wm + gr;
    const int row_hi = row_lo + 8;

    const unsigned Ks_s = (unsigned)__cvta_generic_to_shared(Ks);
    const unsigned Ps_s = (unsigned)__cvta_generic_to_shared(Ps);
    const unsigned kb_base =
        Ks_s + ((((lane & 7) + ((lane >> 4) << 3)) * KS_STR) +
                ((lane >> 3) & 1) * 4) * 4u;
    const unsigned p_base =
        Ps_s + (((wm + (lane & 15)) * KS_STR) + (lane >> 4) * 4) * 4u;

    unsigned qf[8][4];
#pragma unroll
    for (int ks = 0; ks < 8; ks++) {
        int c = hoff + ks * 8 + tg;
        qf[ks][0] = rnb(g_query[(size_t)row_lo * D_ + c] * 0.125f);
        qf[ks][1] = rnb(g_query[(size_t)row_hi * D_ + c] * 0.125f);
        qf[ks][2] = rnb(g_query[(size_t)row_lo * D_ + c + 4] * 0.125f);
        qf[ks][3] = rnb(g_query[(size_t)row_hi * D_ + c + 4] * 0.125f);
    }

    float o[8][4];
#pragma unroll
    for (int i = 0; i < 8; i++)
#pragma unroll
        for (int j = 0; j < 4; j++) o[i][j] = 0.f;
    float m_lo = -INFINITY, m_hi = -INFINITY, l_lo = 0.f, l_hi = 0.f;

    const int tr0 = tid >> 4,           tds0 = (tid & 15) * 4;
    const int tr1 = (512 + tid) >> 4,   tds1 = (tid & 15) * 4;

    float4 kp[2], vp[2];
    kp[0] = *(const float4*)(Kg + (size_t)tr0 * D_ + hoff + tds0);
    vp[0] = *(const float4*)(Vg + (size_t)tr0 * D_ + hoff + tds0);
    kp[1] = *(const float4*)(Kg + (size_t)tr1 * D_ + hoff + tds1);
    vp[1] = *(const float4*)(Vg + (size_t)tr1 * D_ + hoff + tds1);

    for (int kt = 0; kt < KVL; kt += AT_TK) {
        __syncthreads();
        *(uint4*)(Ks + tr0 * KS_STR + tds0) = rnb4(kp[0]);
        *(uint4*)(Vs + tr0 * VS_STR + tds0) = rnb4(vp[0]);
        *(uint4*)(Ks + tr1 * KS_STR + tds1) = rnb4(kp[1]);
        *(uint4*)(Vs + tr1 * VS_STR + tds1) = rnb4(vp[1]);
        if (kt + AT_TK < KVL) {
            const float* kb = Kg + (size_t)(kt + AT_TK) * D_ + hoff;
            const float* vb2 = Vg + (size_t)(kt + AT_TK) * D_ + hoff;
            kp[0] = *(const float4*)(kb + (size_t)tr0 * D_ + tds0);
            vp[0] = *(const float4*)(vb2 + (size_t)tr0 * D_ + tds0);
            kp[1] = *(const float4*)(kb + (size_t)tr1 * D_ + tds1);
            vp[1] = *(const float4*)(vb2 + (size_t)tr1 * D_ + tds1);
        }
        __syncthreads();

        float s[8][4];
#pragma unroll
        for (int i = 0; i < 8; i++)
#pragma unroll
            for (int j = 0; j < 4; j++) s[i][j] = 0.f;
#pragma unroll
        for (int ks = 0; ks < 8; ks++) {
#pragma unroll
            for (int nip = 0; nip < 4; nip++) {
                unsigned b0, b1, b2, b3;
                ldsm4(b0, b1, b2, b3,
                      kb_base + (nip * 16 * KS_STR + ks * 8) * 4u);
                mma_tf32(s[2 * nip], qf[ks][0], qf[ks][1], qf[ks][2], qf[ks][3],
                         b0, b1);
                mma_tf32(s[2 * nip + 1], qf[ks][0], qf[ks][1], qf[ks][2], qf[ks][3],
                         b2, b3);
            }
        }

        float mt_lo = -INFINITY, mt_hi = -INFINITY;
#pragma unroll
        for (int ni = 0; ni < 8; ni++) {
            mt_lo = fmaxf(mt_lo, fmaxf(s[ni][0], s[ni][1]));
            mt_hi = fmaxf(mt_hi, fmaxf(s[ni][2], s[ni][3]));
        }
        mt_lo = fmaxf(mt_lo, __shfl_xor_sync(0xffffffffu, mt_lo, 1));
        mt_lo = fmaxf(mt_lo, __shfl_xor_sync(0xffffffffu, mt_lo, 2));
        mt_hi = fmaxf(mt_hi, __shfl_xor_sync(0xffffffffu, mt_hi, 1));
        mt_hi = fmaxf(mt_hi, __shfl_xor_sync(0xffffffffu, mt_hi, 2));
        float mnew_lo = fmaxf(m_lo, mt_lo);
        float mnew_hi = fmaxf(m_hi, mt_hi);
        float alpha_lo = __expf(m_lo - mnew_lo);
        float alpha_hi = __expf(m_hi - mnew_hi);
        float sum_lo = 0.f, sum_hi = 0.f;
#pragma unroll
        for (int ni = 0; ni < 8; ni++) {
            s[ni][0] = __expf(s[ni][0] - mnew_lo);
            s[ni][1] = __expf(s[ni][1] - mnew_lo);
            s[ni][2] = __expf(s[ni][2] - mnew_hi);
            s[ni][3] = __expf(s[ni][3] - mnew_hi);
            sum_lo += s[ni][0] + s[ni][1];
            sum_hi += s[ni][2] + s[ni][3];
        }
        sum_lo += __shfl_xor_sync(0xffffffffu, sum_lo, 1);
        sum_lo += __shfl_xor_sync(0xffffffffu, sum_lo, 2);
        sum_hi += __shfl_xor_sync(0xffffffffu, sum_hi, 1);
        sum_hi += __shfl_xor_sync(0xffffffffu, sum_hi, 2);
        l_lo = l_lo * alpha_lo + sum_lo;
        l_hi = l_hi * alpha_hi + sum_hi;
        m_lo = mnew_lo;
        m_hi = mnew_hi;
#pragma unroll
        for (int ni = 0; ni < 8; ni++) {
            o[ni][0] *= alpha_lo; o[ni][1] *= alpha_lo;
            o[ni][2] *= alpha_hi; o[ni][3] *= alpha_hi;
        }

#pragma unroll
        for (int ni = 0; ni < 8; ni++) {
            int cc = ni * 8 + 2 * tg;
            *(uint2*)(Ps + (wm + gr) * KS_STR + cc) =
                make_uint2(rnb(s[ni][0]), rnb(s[ni][1]));
            *(uint2*)(Ps + (wm + gr + 8) * KS_STR + cc) =
                make_uint2(rnb(s[ni][2]), rnb(s[ni][3]));
        }
        __syncwarp();

#pragma unroll
        for (int ks = 0; ks < 8; ks++) {
            unsigned a0, a1, a2, a3;
            ldsm4(a0, a1, a2, a3, p_base + (ks * 8) * 4u);
            const unsigned* vb = Vs + (ks * 8 + tg) * VS_STR + gr;
#pragma unroll
            for (int ni = 0; ni < 8; ni++) {
                unsigned b0 = vb[ni * 8];
                unsigned b1 = vb[4 * VS_STR + ni * 8];
                mma_tf32(o[ni], a0, a1, a2, a3, b0, b1);
            }
        }
    }

    float inv_lo = 1.0f / l_lo;
    float inv_hi = 1.0f / l_hi;
#pragma unroll
    for (int ni = 0; ni < 8; ni++) {
        int col = hoff + ni * 8 + 2 * tg;
        *(float2*)(g_attn + (size_t)row_lo * D_ + col) =
            make_float2(o[ni][0] * inv_lo, o[ni][1] * inv_lo);
        *(float2*)(g_attn + (size_t)row_hi * D_ + col) =
            make_float2(o[ni][2] * inv_hi, o[ni][3] * inv_hi);
    }
}

#define ATTN_SMEM ((AT_TK * KS_STR + AT_TK * VS_STR + AT_TQ * KS_STR) * (int)sizeof(unsigned))

// ---------------------------------------------------------------------------
extern "C" void kernel_launch(void* const* d_in, const int* in_sizes, int n_in,
                              void* d_out, int out_size) {
    const float* utt = (const float*)d_in[0];
    const float* rc  = (const float*)d_in[1];
    const float* mem = (const float*)d_in[2];
    const float* lck = (const float*)d_in[3];
    const float* lcv = (const float*)d_in[4];
    const float* Wq  = (const float*)d_in[5];
    const float* bq  = (const float*)d_in[6];
    const float* Wkv = (const float*)d_in[7];
    const float* bkv = (const float*)d_in[8];
    const float* Wo  = (const float*)d_in[9];
    const float* bo  = (const float*)d_in[10];

    float* outBuf = (float*)d_out;                       // [2304,1024]
    float* keyBuf = outBuf + (size_t)QL * D_;            // [3840,1024]
    float* valBuf = keyBuf + (size_t)KVL * D_;           // [3840,1024]

    cudaFuncSetAttribute(attn_kernel, cudaFuncAttributeMaxDynamicSharedMemorySize,
                         ATTN_SMEM);
    cudaFuncSetAttribute(gemm_q_kernel, cudaFuncAttributeMaxDynamicSharedMemorySize,
                         GEMM_SMEM);
    cudaFuncSetAttribute(gemm_kv_kernel, cudaFuncAttributeMaxDynamicSharedMemorySize,
                         GEMM_SMEM);
    cudaFuncSetAttribute(gemm_o_kernel, cudaFuncAttributeMaxDynamicSharedMemorySize,
                         GEMM_SMEM);

    gemm_q_kernel<<<dim3(QL / BM, D_ / BN), 256, GEMM_SMEM>>>(rc, utt, Wq, bq);
    gemm_kv_kernel<<<dim3((M_ + R_ + U_) / BM, 2 * D_ / BN), 256, GEMM_SMEM>>>(
        mem, rc, utt, Wkv, bkv, keyBuf, valBuf);
    cudaMemcpyAsync(keyBuf + (size_t)(M_ + R_) * D_, lck,
                    (size_t)L_ * D_ * sizeof(float), cudaMemcpyDeviceToDevice);
    cudaMemcpyAsync(valBuf + (size_t)(M_ + R_) * D_, lcv,
                    (size_t)L_ * D_ * sizeof(float), cudaMemcpyDeviceToDevice);
    attn_kernel<<<dim3(QL / AT_TQ, NH), 512, ATTN_SMEM>>>(keyBuf, valBuf);
    gemm_o_kernel<<<dim3(QL / BM, D_ / BN), 256, GEMM_SMEM>>>(Wo, bo, outBuf);
}